// round 3
// baseline (speedup 1.0000x reference)
#include <cuda_runtime.h>
#include <cuda_bf16.h>
#include <math.h>

// ---------------------------------------------------------------------------
// PET MLEM step: TOR forward projection + listmode backprojection, 3 LOR sets.
// R3: plane-pairing -> red.global.add.v2.f32 for the backprojection scatter
// when adjacent planes share a center cell (~50%); paired bf16x2 gathers too.
// ---------------------------------------------------------------------------

#define NG   128
#define NG2  (128 * 128)
#define NG3  (128 * 128 * 128)

__device__ __nv_bfloat16 g_imgB [NG3];  // bf16 image, native layout
__device__ __nv_bfloat16 g_imgBT[NG3];  // bf16, imgBT[a][b][c] = image[a][c][b]
__device__ float g_bp [NG3];            // accumulator (z,y dirs)
__device__ float g_bpT[NG3];            // transposed accumulator (x dir)

__constant__ float C_VOX    = 1.671875f;
__constant__ float C_XMIN   = -107.0f;
__constant__ float C_INV2S2 = 0.561975285171464f;   // pi / (2 * vox^2)

__device__ __forceinline__ void red_add_v2(float* p, float a, float b) {
    asm volatile("red.global.add.v2.f32 [%0], {%1, %2};"
                 :: "l"(p), "f"(a), "f"(b) : "memory");
}

// ---------------------------------------------------------------------------
__global__ void prep_kernel(const float* __restrict__ image) {
    int tid = blockIdx.x * blockDim.x + threadIdx.x;
    if (tid >= NG3) return;
    int a = tid >> 14;
    int b = (tid >> 7) & 127;
    int c = tid & 127;
    __nv_bfloat16 h = __float2bfloat16(image[tid]);
    g_imgB[tid] = h;
    g_imgBT[(a << 14) + (c << 7) + b] = h;
}

// ---------------------------------------------------------------------------
// One warp per LOR. Lane L owns planes {2L, 2L+1} and {2L+64, 2L+65}.
// voxel (i, j, plane k) address = i*SI + j*SJ + k
// ---------------------------------------------------------------------------
template <int SI, int SJ>
__global__ __launch_bounds__(256)
void lor_kernel(const float* __restrict__ lors,   // [6, n] row-major
                const __nv_bfloat16* __restrict__ img,
                float* __restrict__ bp,
                int n) {
    const int warp = blockIdx.x * 8 + (threadIdx.x >> 5);
    if (warp >= n) return;
    const int lane = threadIdx.x & 31;

    const float p1x = lors[0 * n + warp];
    const float p1y = lors[1 * n + warp];
    const float p1z = lors[2 * n + warp];
    const float p2x = lors[3 * n + warp];
    const float p2y = lors[4 * n + warp];
    const float p2z = lors[5 * n + warp];

    const float dx  = p2x - p1x;
    const float dy  = p2y - p1y;
    const float dzr = p2z - p1z;
    const float L   = sqrtf(dx * dx + dy * dy + dzr * dzr);
    const float dz  = (fabsf(dzr) < 1e-6f) ? 1e-6f : dzr;
    const float dl  = C_VOX * L / fabsf(dz);

    float ex[2][2][3];   // [half][plane-in-pair][offset]
    float ey[2][2][3];
    int   ib[2][2];
    int   jb[2][2];
    bool  tk[2][2];
    bool  mt[2];

    float acc = 0.0f;

#pragma unroll
    for (int h = 0; h < 2; h++) {
        const int kbase = 2 * lane + 64 * h;
#pragma unroll
        for (int p = 0; p < 2; p++) {
            const int   k  = kbase + p;
            const float zc = C_XMIN + ((float)k + 0.5f) * C_VOX;
            const float t  = (zc - p1z) / dz;
            const bool  tok = (t >= 0.0f) && (t <= 1.0f);
            const float xs = __fadd_rn(p1x, __fmul_rn(t, dx));
            const float ys = __fadd_rn(p1y, __fmul_rn(t, dy));
            const float fi = __fadd_rn(__fdiv_rn(__fsub_rn(xs, C_XMIN), C_VOX), -0.5f);
            const float fj = __fadd_rn(__fdiv_rn(__fsub_rn(ys, C_XMIN), C_VOX), -0.5f);
            const int i0 = __float2int_rn(fi);
            const int j0 = __float2int_rn(fj);
            ib[h][p] = i0;
            jb[h][p] = j0;
            tk[h][p] = tok;
            const float axc = (float)i0 - fi;
            const float ayc = (float)j0 - fj;
#pragma unroll
            for (int o = 0; o < 3; o++) {
                const float du = (axc + (float)(o - 1)) * C_VOX;
                const float eu = __expf(-du * du * C_INV2S2);
                const int   ii = i0 + o - 1;
                ex[h][p][o] = (tok && ii >= 0 && ii < NG) ? eu : 0.0f;

                const float dv = (ayc + (float)(o - 1)) * C_VOX;
                const float ev = __expf(-dv * dv * C_INV2S2);
                const int   jj = j0 + o - 1;
                ey[h][p][o] = (jj >= 0 && jj < NG) ? ev : 0.0f;
            }
        }
        mt[h] = (ib[h][0] == ib[h][1]) && (jb[h][0] == jb[h][1]);

        if (mt[h]) {
            // paired gather: one bf16x2 load covers both planes
#pragma unroll
            for (int oi = 0; oi < 3; oi++) {
                const int ii = min(max(ib[h][0] + oi - 1, 0), NG - 1);
                float ina = 0.0f, inb = 0.0f;
#pragma unroll
                for (int oj = 0; oj < 3; oj++) {
                    const int jj = min(max(jb[h][0] + oj - 1, 0), NG - 1);
                    const __nv_bfloat162 v = __ldg(
                        (const __nv_bfloat162*)&img[ii * SI + jj * SJ + kbase]);
                    ina = fmaf(ey[h][0][oj], __bfloat162float(v.x), ina);
                    inb = fmaf(ey[h][1][oj], __bfloat162float(v.y), inb);
                }
                acc = fmaf(ex[h][0][oi], ina, acc);
                acc = fmaf(ex[h][1][oi], inb, acc);
            }
        } else {
#pragma unroll
            for (int p = 0; p < 2; p++) {
                if (tk[h][p]) {
#pragma unroll
                    for (int oi = 0; oi < 3; oi++) {
                        const int ii = min(max(ib[h][p] + oi - 1, 0), NG - 1);
                        float inner = 0.0f;
#pragma unroll
                        for (int oj = 0; oj < 3; oj++) {
                            const int jj = min(max(jb[h][p] + oj - 1, 0), NG - 1);
                            const float v = __bfloat162float(
                                __ldg(&img[ii * SI + jj * SJ + kbase + p]));
                            inner = fmaf(ey[h][p][oj], v, inner);
                        }
                        acc = fmaf(ex[h][p][oi], inner, acc);
                    }
                }
            }
        }
    }

    // warp-reduce line integral
#pragma unroll
    for (int s = 16; s > 0; s >>= 1)
        acc += __shfl_xor_sync(0xffffffffu, acc, s);

    const float proj = acc * dl;
    const float scl  = dl / (proj + 1e-8f);

    // backprojection scatter
#pragma unroll
    for (int h = 0; h < 2; h++) {
        const int kbase = 2 * lane + 64 * h;
        if (mt[h]) {
#pragma unroll
            for (int oi = 0; oi < 3; oi++) {
                const int ii = min(max(ib[h][0] + oi - 1, 0), NG - 1);
#pragma unroll
                for (int oj = 0; oj < 3; oj++) {
                    const float wa = ex[h][0][oi] * ey[h][0][oj];
                    const float wb = ex[h][1][oi] * ey[h][1][oj];
                    if (wa != 0.0f || wb != 0.0f) {
                        const int jj = min(max(jb[h][0] + oj - 1, 0), NG - 1);
                        red_add_v2(&bp[ii * SI + jj * SJ + kbase],
                                   wa * scl, wb * scl);
                    }
                }
            }
        } else {
#pragma unroll
            for (int p = 0; p < 2; p++) {
#pragma unroll
                for (int oi = 0; oi < 3; oi++) {
                    const float exi = ex[h][p][oi];
                    const int   ii  = min(max(ib[h][p] + oi - 1, 0), NG - 1);
#pragma unroll
                    for (int oj = 0; oj < 3; oj++) {
                        const float w = exi * ey[h][p][oj];
                        if (w != 0.0f) {
                            const int jj = min(max(jb[h][p] + oj - 1, 0), NG - 1);
                            atomicAdd(&bp[ii * SI + jj * SJ + kbase + p], w * scl);
                        }
                    }
                }
            }
        }
    }
}

// ---------------------------------------------------------------------------
__global__ void combine_kernel(const float* __restrict__ image,
                               const float* __restrict__ eff,
                               float* __restrict__ out) {
    int tid = blockIdx.x * blockDim.x + threadIdx.x;
    if (tid >= NG3) return;
    int a = tid >> 14;
    int b = (tid >> 7) & 127;
    int c = tid & 127;
    float bpsum = g_bp[tid] + __ldg(&g_bpT[(a << 14) + (c << 7) + b]);
    out[tid] = image[tid] / (eff[tid] + 1e-8f) * bpsum;
}

// ---------------------------------------------------------------------------
extern "C" void kernel_launch(void* const* d_in, const int* in_sizes, int n_in,
                              void* d_out, int out_size) {
    const float* image = (const float*)d_in[0];
    const float* eff   = (const float*)d_in[1];
    const float* xl    = (const float*)d_in[2];
    const float* yl    = (const float*)d_in[3];
    const float* zl    = (const float*)d_in[4];
    float*       out   = (float*)d_out;

    const int n = in_sizes[2] / 6;   // 65536

    void* imgB_p  = nullptr;
    void* imgBT_p = nullptr;
    void* bp_p    = nullptr;
    void* bpT_p   = nullptr;
    cudaGetSymbolAddress(&imgB_p,  g_imgB);
    cudaGetSymbolAddress(&imgBT_p, g_imgBT);
    cudaGetSymbolAddress(&bp_p,    g_bp);
    cudaGetSymbolAddress(&bpT_p,   g_bpT);

    cudaMemsetAsync(bp_p,  0, NG3 * sizeof(float));
    cudaMemsetAsync(bpT_p, 0, NG3 * sizeof(float));

    prep_kernel<<<NG3 / 256, 256>>>(image);

    const int nb = (n + 7) / 8;   // 8 warps (LORs) per 256-thread block

    lor_kernel<16384, 128><<<nb, 256>>>(zl, (const __nv_bfloat16*)imgB_p,
                                        (float*)bp_p, n);
    lor_kernel<128, 16384><<<nb, 256>>>(yl, (const __nv_bfloat16*)imgB_p,
                                        (float*)bp_p, n);
    lor_kernel<128, 16384><<<nb, 256>>>(xl, (const __nv_bfloat16*)imgBT_p,
                                        (float*)bpT_p, n);

    combine_kernel<<<NG3 / 256, 256>>>(image, eff, out);
}

// round 4
// speedup vs baseline: 1.2887x; 1.2887x over previous
#include <cuda_runtime.h>
#include <cuda_bf16.h>
#include <math.h>

// ---------------------------------------------------------------------------
// PET MLEM step. R4: backprojection accumulated in fixed-point u32 pairs
// packed into u64 words (planes 2m / 2m+1), scattered with red.global.add.u64
// over a branch-free 4x4 union footprint -> ~0.61x atomic element count.
// ---------------------------------------------------------------------------

#define NG   128
#define NG3  (128 * 128 * 128)

typedef unsigned long long u64;
typedef unsigned int       u32;

__device__ __nv_bfloat16 g_imgB [NG3];   // bf16 image, native layout
__device__ __nv_bfloat16 g_imgBT[NG3];   // imgBT[a][b][c] = image[a][c][b]
__device__ u64 g_bpP [NG3 / 2];          // packed accumulator (z,y dirs)
__device__ u64 g_bpPT[NG3 / 2];          // packed transposed accumulator (x)

__constant__ float C_VOX    = 1.671875f;
__constant__ float C_XMIN   = -107.0f;
__constant__ float C_INV2S2 = 0.561975285171464f;   // pi / (2 * vox^2)

#define FP_SCALE     4194304.0f            // 2^22
#define FP_INV_SCALE 2.384185791015625e-7f // 2^-22

__device__ __forceinline__ void red_add_u64(u64* p, u64 v) {
    asm volatile("red.global.add.u64 [%0], %1;" :: "l"(p), "l"(v) : "memory");
}

// ---------------------------------------------------------------------------
__global__ void prep_kernel(const float* __restrict__ image) {
    int tid = blockIdx.x * blockDim.x + threadIdx.x;
    if (tid >= NG3) return;
    int a = tid >> 14;
    int b = (tid >> 7) & 127;
    int c = tid & 127;
    __nv_bfloat16 h = __float2bfloat16(image[tid]);
    g_imgB[tid] = h;
    g_imgBT[(a << 14) + (c << 7) + b] = h;
}

// ---------------------------------------------------------------------------
// One warp per LOR. Lane L owns plane pairs (2L, 2L+1) and (2L+64, 2L+65).
// img voxel (i, j, k) at i*SI + j*SJ + k ; packed word (i,j,m=k/2) at
// i*(SI/2) + j*(SJ/2) + m, low half = even plane.
// ---------------------------------------------------------------------------
template <int SI, int SJ>
__global__ __launch_bounds__(256)
void lor_kernel(const float* __restrict__ lors,   // [6, n] row-major
                const __nv_bfloat16* __restrict__ img,
                u64* __restrict__ bp,
                int n) {
    constexpr int SIW = SI / 2;
    constexpr int SJW = SJ / 2;

    const int warp = blockIdx.x * 8 + (threadIdx.x >> 5);
    if (warp >= n) return;
    const int lane = threadIdx.x & 31;

    const float p1x = lors[0 * n + warp];
    const float p1y = lors[1 * n + warp];
    const float p1z = lors[2 * n + warp];
    const float p2x = lors[3 * n + warp];
    const float p2y = lors[4 * n + warp];
    const float p2z = lors[5 * n + warp];

    const float dx  = p2x - p1x;
    const float dy  = p2y - p1y;
    const float dzr = p2z - p1z;
    const float L   = sqrtf(dx * dx + dy * dy + dzr * dzr);
    const float dz  = (fabsf(dzr) < 1e-6f) ? 1e-6f : dzr;
    const float dl  = C_VOX * L / fabsf(dz);

    float ex[2][2][3];   // [half][plane-in-pair][offset]
    float ey[2][2][3];
    int   ib[2][2];
    int   jb[2][2];

    float acc = 0.0f;

#pragma unroll
    for (int h = 0; h < 2; h++) {
        const int kA = 2 * lane + 64 * h;
        bool tokk[2];
#pragma unroll
        for (int p = 0; p < 2; p++) {
            const int   k  = kA + p;
            const float zc = C_XMIN + ((float)k + 0.5f) * C_VOX;
            const float t  = (zc - p1z) / dz;
            const bool  tok = (t >= 0.0f) && (t <= 1.0f);
            const float xs = __fadd_rn(p1x, __fmul_rn(t, dx));
            const float ys = __fadd_rn(p1y, __fmul_rn(t, dy));
            const float fi = __fadd_rn(__fdiv_rn(__fsub_rn(xs, C_XMIN), C_VOX), -0.5f);
            const float fj = __fadd_rn(__fdiv_rn(__fsub_rn(ys, C_XMIN), C_VOX), -0.5f);
            const int i0 = __float2int_rn(fi);
            const int j0 = __float2int_rn(fj);
            ib[h][p] = i0;
            jb[h][p] = j0;
            tokk[p]  = tok;
            const float axc = (float)i0 - fi;
            const float ayc = (float)j0 - fj;
#pragma unroll
            for (int o = 0; o < 3; o++) {
                const float du = (axc + (float)(o - 1)) * C_VOX;
                const float eu = __expf(-du * du * C_INV2S2);
                const int   ii = i0 + o - 1;
                ex[h][p][o] = (tok && ii >= 0 && ii < NG) ? eu : 0.0f;

                const float dv = (ayc + (float)(o - 1)) * C_VOX;
                const float ev = __expf(-dv * dv * C_INV2S2);
                const int   jj = j0 + o - 1;
                ey[h][p][o] = (jj >= 0 && jj < NG) ? ev : 0.0f;
            }
        }
        // sanitize centers so the scatter union box stays 4x4 even when one
        // plane is out of t-range (its weights are already all zero)
        if (!tokk[1]) { ib[h][1] = ib[h][0]; jb[h][1] = jb[h][0]; }
        if (!tokk[0]) { ib[h][0] = ib[h][1]; jb[h][0] = jb[h][1]; }

        // forward gather (bf16)
#pragma unroll
        for (int p = 0; p < 2; p++) {
            if (tokk[p]) {
                const int k = kA + p;
#pragma unroll
                for (int oi = 0; oi < 3; oi++) {
                    const int ii = min(max(ib[h][p] + oi - 1, 0), NG - 1);
                    float inner = 0.0f;
#pragma unroll
                    for (int oj = 0; oj < 3; oj++) {
                        const int jj = min(max(jb[h][p] + oj - 1, 0), NG - 1);
                        const float v = __bfloat162float(
                            __ldg(&img[ii * SI + jj * SJ + k]));
                        inner = fmaf(ey[h][p][oj], v, inner);
                    }
                    acc = fmaf(ex[h][p][oi], inner, acc);
                }
            }
        }
    }

    // warp-reduce line integral
#pragma unroll
    for (int s = 16; s > 0; s >>= 1)
        acc += __shfl_xor_sync(0xffffffffu, acc, s);

    const float proj = acc * dl;
    const float scl  = dl / (proj + 1e-8f);
    const float s2   = scl * FP_SCALE;

    // backprojection scatter: branch-free 4x4 union box, packed u64 atomics
#pragma unroll
    for (int h = 0; h < 2; h++) {
        const int m  = lane + 32 * h;            // word index along ray axis
        const int iA = ib[h][0], iB = ib[h][1];
        const int jA = jb[h][0], jB = jb[h][1];
        const int bi = min(iA, iB) - 1;
        const int bj = min(jA, jB) - 1;

        // per-row weights for the 4 box columns (select chains: static idx)
        float eyAv[4], eyBv[4];
#pragma unroll
        for (int v = 0; v < 4; v++) {
            const int cj = bj + v;
            float wa = 0.0f, wb = 0.0f;
            if (cj == jA - 1) wa = ey[h][0][0];
            else if (cj == jA) wa = ey[h][0][1];
            else if (cj == jA + 1) wa = ey[h][0][2];
            if (cj == jB - 1) wb = ey[h][1][0];
            else if (cj == jB) wb = ey[h][1][1];
            else if (cj == jB + 1) wb = ey[h][1][2];
            eyAv[v] = wa;
            eyBv[v] = wb;
        }

#pragma unroll
        for (int u = 0; u < 4; u++) {
            const int ci = bi + u;
            float exA = 0.0f, exB = 0.0f;
            if (ci == iA - 1) exA = ex[h][0][0];
            else if (ci == iA) exA = ex[h][0][1];
            else if (ci == iA + 1) exA = ex[h][0][2];
            if (ci == iB - 1) exB = ex[h][1][0];
            else if (ci == iB) exB = ex[h][1][1];
            else if (ci == iB + 1) exB = ex[h][1][2];
            const float exAs = exA * s2;
            const float exBs = exB * s2;
            u64* row = bp + (long long)ci * SIW + m;
#pragma unroll
            for (int v = 0; v < 4; v++) {
                const u32 lo = __float2uint_rn(exAs * eyAv[v]);
                const u32 hi = __float2uint_rn(exBs * eyBv[v]);
                const u64 val = (u64)lo | ((u64)hi << 32);
                if (val != 0ull) {
                    red_add_u64(row + (long long)(bj + v) * SJW, val);
                }
            }
        }
    }
}

// ---------------------------------------------------------------------------
// combine: out = image / (eff + 1e-8) * (bp + bpT^T), unpacking fixed-point
// ---------------------------------------------------------------------------
__global__ void combine_kernel(const float* __restrict__ image,
                               const float* __restrict__ eff,
                               float* __restrict__ out) {
    int tid = blockIdx.x * blockDim.x + threadIdx.x;
    if (tid >= NG3) return;
    int a = tid >> 14;
    int b = (tid >> 7) & 127;
    int c = tid & 127;

    // native: voxel (a,b,c) -> word tid>>1, half c&1
    const u64 wz = g_bpP[tid >> 1];
    const float vz = __uint2float_rn((u32)(wz >> (32 * (c & 1))));

    // transposed: voxel (a,b,c) lives in bpT frame at word a*8192 + c*64 + b/2,
    // half b&1
    const u64 wt = __ldg(&g_bpPT[(a << 13) + (c << 6) + (b >> 1)]);
    const float vt = __uint2float_rn((u32)(wt >> (32 * (b & 1))));

    const float bpsum = (vz + vt) * FP_INV_SCALE;
    out[tid] = image[tid] / (eff[tid] + 1e-8f) * bpsum;
}

// ---------------------------------------------------------------------------
extern "C" void kernel_launch(void* const* d_in, const int* in_sizes, int n_in,
                              void* d_out, int out_size) {
    const float* image = (const float*)d_in[0];
    const float* eff   = (const float*)d_in[1];
    const float* xl    = (const float*)d_in[2];
    const float* yl    = (const float*)d_in[3];
    const float* zl    = (const float*)d_in[4];
    float*       out   = (float*)d_out;

    const int n = in_sizes[2] / 6;   // 65536

    void* imgB_p  = nullptr;
    void* imgBT_p = nullptr;
    void* bpP_p   = nullptr;
    void* bpPT_p  = nullptr;
    cudaGetSymbolAddress(&imgB_p,  g_imgB);
    cudaGetSymbolAddress(&imgBT_p, g_imgBT);
    cudaGetSymbolAddress(&bpP_p,   g_bpP);
    cudaGetSymbolAddress(&bpPT_p,  g_bpPT);

    cudaMemsetAsync(bpP_p,  0, (NG3 / 2) * sizeof(u64));
    cudaMemsetAsync(bpPT_p, 0, (NG3 / 2) * sizeof(u64));

    prep_kernel<<<NG3 / 256, 256>>>(image);

    const int nb = (n + 7) / 8;   // 8 warps (LORs) per 256-thread block

    // z: i stride 16384, j stride 128 (f32-element units)
    lor_kernel<16384, 128><<<nb, 256>>>(zl, (const __nv_bfloat16*)imgB_p,
                                        (u64*)bpP_p, n);
    // y: i -> image axis1 (128), j -> axis0 (16384)
    lor_kernel<128, 16384><<<nb, 256>>>(yl, (const __nv_bfloat16*)imgB_p,
                                        (u64*)bpP_p, n);
    // x: transposed image + transposed packed accumulator
    lor_kernel<128, 16384><<<nb, 256>>>(xl, (const __nv_bfloat16*)imgBT_p,
                                        (u64*)bpPT_p, n);

    combine_kernel<<<NG3 / 256, 256>>>(image, eff, out);
}

// round 8
// speedup vs baseline: 1.4545x; 1.1287x over previous
#include <cuda_runtime.h>
#include <cuda_bf16.h>
#include <math.h>

// ---------------------------------------------------------------------------
// PET MLEM step. R5: gather via pre-packed bf16 j-triples (8B loads, 3 instead
// of 9 loads per plane); SWAP trick maps all 3 directions onto one packed
// layout orientation; scatter = scalar fp32 atomics (best measured).
// ---------------------------------------------------------------------------

#define NG   128
#define NG3  (128 * 128 * 128)

typedef unsigned int u32;

// packed[i][j][k] = { bf16 img[i][j-1][k], bf16 img[i][j][k], bf16 img[i][j+1][k], 0 }
__device__ uint2 g_img4 [NG3];   // native orientation  (z and y directions)
__device__ uint2 g_img4T[NG3];   // transposed frame    (x direction)
__device__ float g_bp  [NG3];    // accumulator (z, y)
__device__ float g_bpT [NG3];    // transposed accumulator (x)

__constant__ float C_VOX    = 1.671875f;
__constant__ float C_XMIN   = -107.0f;
__constant__ float C_INV2S2 = 0.561975285171464f;   // pi / (2 * vox^2)

__device__ __forceinline__ u32 pack2(float a, float b) {
    __nv_bfloat162 h = __floats2bfloat162_rn(a, b);
    return *(u32*)&h;
}

// ---------------------------------------------------------------------------
// prep native: img4[i][j][k] packs image[i][j-1..j+1][k]; k fast, coalesced.
// ---------------------------------------------------------------------------
__global__ void prep_kernel(const float* __restrict__ image) {
    int tid = blockIdx.x * blockDim.x + threadIdx.x;
    if (tid >= NG3) return;
    int i = tid >> 14;
    int j = (tid >> 7) & 127;
    int k = tid & 127;
    float vm = (j > 0)   ? image[(i << 14) + ((j - 1) << 7) + k] : 0.0f;
    float v0 =             image[tid];
    float vp = (j < 127) ? image[(i << 14) + ((j + 1) << 7) + k] : 0.0f;
    uint2 w;
    w.x = pack2(vm, v0);
    w.y = pack2(vp, 0.0f);
    g_img4[tid] = w;
}

// ---------------------------------------------------------------------------
// prep transposed frame: imgT[a][b][c] = image[a][c][b];
// img4T[a][b][c] packs imgT[a][b-1..b+1][c] = image[a][c][b-1..b+1].
// Thread order (a, c, b) with b fast -> coalesced reads, strided 8B stores.
// ---------------------------------------------------------------------------
__global__ void prepT_kernel(const float* __restrict__ image) {
    int tid = blockIdx.x * blockDim.x + threadIdx.x;
    if (tid >= NG3) return;
    int a = tid >> 14;
    int c = (tid >> 7) & 127;
    int b = tid & 127;
    const float* row = image + (a << 14) + (c << 7);
    float vm = (b > 0)   ? row[b - 1] : 0.0f;
    float v0 =             row[b];
    float vp = (b < 127) ? row[b + 1] : 0.0f;
    uint2 w;
    w.x = pack2(vm, v0);
    w.y = pack2(vp, 0.0f);
    g_img4T[(a << 14) + (b << 7) + c] = w;
}

// ---------------------------------------------------------------------------
// One warp per LOR; lane L owns planes {L, L+32, L+64, L+96}.
// All directions use SI=16384 (i), SJ=128 (j), k fast. SWAP exchanges the
// two transverse LOR components so j is always the packed axis.
// ---------------------------------------------------------------------------
template <bool SWAP>
__global__ __launch_bounds__(256)
void lor_kernel(const float* __restrict__ lors,   // [6, n] row-major
                const uint2* __restrict__ img4,
                float* __restrict__ bp,
                int n) {
    const int warp = blockIdx.x * 8 + (threadIdx.x >> 5);
    if (warp >= n) return;
    const int lane = threadIdx.x & 31;

    float p1x = lors[0 * n + warp];
    float p1y = lors[1 * n + warp];
    const float p1z = lors[2 * n + warp];
    float p2x = lors[3 * n + warp];
    float p2y = lors[4 * n + warp];
    const float p2z = lors[5 * n + warp];
    if (SWAP) {
        float t;
        t = p1x; p1x = p1y; p1y = t;
        t = p2x; p2x = p2y; p2y = t;
    }

    const float dx  = p2x - p1x;
    const float dy  = p2y - p1y;
    const float dzr = p2z - p1z;
    const float L   = sqrtf(dx * dx + dy * dy + dzr * dzr);
    const float dz  = (fabsf(dzr) < 1e-6f) ? 1e-6f : dzr;
    const float dl  = C_VOX * L / fabsf(dz);

    float ex[4][3];
    float ey[4][3];
    int   ib[4];
    int   jb[4];

    float acc = 0.0f;

#pragma unroll
    for (int q = 0; q < 4; q++) {
        const int   k  = lane + 32 * q;
        const float zc = C_XMIN + ((float)k + 0.5f) * C_VOX;
        const float t  = (zc - p1z) / dz;
        const bool  tok = (t >= 0.0f) && (t <= 1.0f);
        const float xs = __fadd_rn(p1x, __fmul_rn(t, dx));
        const float ys = __fadd_rn(p1y, __fmul_rn(t, dy));
        const float fi = __fadd_rn(__fdiv_rn(__fsub_rn(xs, C_XMIN), C_VOX), -0.5f);
        const float fj = __fadd_rn(__fdiv_rn(__fsub_rn(ys, C_XMIN), C_VOX), -0.5f);
        const int i0 = __float2int_rn(fi);
        const int j0 = __float2int_rn(fj);
        ib[q] = i0;
        jb[q] = j0;
        const float axc = (float)i0 - fi;
        const float ayc = (float)j0 - fj;

#pragma unroll
        for (int o = 0; o < 3; o++) {
            const float du = (axc + (float)(o - 1)) * C_VOX;
            const float eu = __expf(-du * du * C_INV2S2);
            const int   ii = i0 + o - 1;
            ex[q][o] = (tok && ii >= 0 && ii < NG) ? eu : 0.0f;

            const float dv = (ayc + (float)(o - 1)) * C_VOX;
            const float ev = __expf(-dv * dv * C_INV2S2);
            const int   jj = j0 + o - 1;
            ey[q][o] = (jj >= 0 && jj < NG) ? ev : 0.0f;
        }

        // gather: 3 packed 8B loads (j-triples), interior guaranteed when tok
        if (tok) {
            const float e0 = ey[q][0], e1 = ey[q][1], e2 = ey[q][2];
#pragma unroll
            for (int oi = 0; oi < 3; oi++) {
                const int ii = ib[q] + oi - 1;
                const uint2 w = __ldg(&img4[(ii << 14) + (j0 << 7) + k]);
                const __nv_bfloat162 ab = *(const __nv_bfloat162*)&w.x;
                const __nv_bfloat162 cd = *(const __nv_bfloat162*)&w.y;
                float inner;
                inner = __fmul_rn(e0, __bfloat162float(ab.x));
                inner = fmaf(e1, __bfloat162float(ab.y), inner);
                inner = fmaf(e2, __bfloat162float(cd.x), inner);
                acc = fmaf(ex[q][oi], inner, acc);
            }
        }
    }

    // warp-reduce line integral
#pragma unroll
    for (int s = 16; s > 0; s >>= 1)
        acc += __shfl_xor_sync(0xffffffffu, acc, s);

    const float proj = acc * dl;
    const float scl  = dl / (proj + 1e-8f);

    // scatter: scalar fp32 atomics (9 per plane)
#pragma unroll
    for (int q = 0; q < 4; q++) {
        const int k = lane + 32 * q;
#pragma unroll
        for (int oi = 0; oi < 3; oi++) {
            const float exi = ex[q][oi] * scl;
            const int   ii  = ib[q] + oi - 1;
#pragma unroll
            for (int oj = 0; oj < 3; oj++) {
                const float w = exi * ey[q][oj];
                if (w != 0.0f) {
                    const int jj = jb[q] + oj - 1;
                    atomicAdd(&bp[(ii << 14) + (jj << 7) + k], w);
                }
            }
        }
    }
}

// ---------------------------------------------------------------------------
// combine: out = image / (eff + 1e-8) * (bp + bpT^T)
// ---------------------------------------------------------------------------
__global__ void combine_kernel(const float* __restrict__ image,
                               const float* __restrict__ eff,
                               float* __restrict__ out) {
    int tid = blockIdx.x * blockDim.x + threadIdx.x;
    if (tid >= NG3) return;
    int a = tid >> 14;
    int b = (tid >> 7) & 127;
    int c = tid & 127;
    float bpsum = g_bp[tid] + __ldg(&g_bpT[(a << 14) + (c << 7) + b]);
    out[tid] = image[tid] / (eff[tid] + 1e-8f) * bpsum;
}

// ---------------------------------------------------------------------------
extern "C" void kernel_launch(void* const* d_in, const int* in_sizes, int n_in,
                              void* d_out, int out_size) {
    const float* image = (const float*)d_in[0];
    const float* eff   = (const float*)d_in[1];
    const float* xl    = (const float*)d_in[2];
    const float* yl    = (const float*)d_in[3];
    const float* zl    = (const float*)d_in[4];
    float*       out   = (float*)d_out;

    const int n = in_sizes[2] / 6;   // 65536

    void* img4_p  = nullptr;
    void* img4T_p = nullptr;
    void* bp_p    = nullptr;
    void* bpT_p   = nullptr;
    cudaGetSymbolAddress(&img4_p,  g_img4);
    cudaGetSymbolAddress(&img4T_p, g_img4T);
    cudaGetSymbolAddress(&bp_p,    g_bp);
    cudaGetSymbolAddress(&bpT_p,   g_bpT);

    cudaMemsetAsync(bp_p,  0, NG3 * sizeof(float));
    cudaMemsetAsync(bpT_p, 0, NG3 * sizeof(float));

    prep_kernel <<<NG3 / 256, 256>>>(image);
    prepT_kernel<<<NG3 / 256, 256>>>(image);

    const int nb = (n + 7) / 8;   // 8 warps (LORs) per 256-thread block

    // z: comp0 -> i (axis0), comp1 -> j (axis1, packed)
    lor_kernel<false><<<nb, 256>>>(zl, (const uint2*)img4_p, (float*)bp_p, n);
    // y: swapped -> comp1 -> i (axis0), comp0 -> j (axis1, packed); same voxels
    lor_kernel<true><<<nb, 256>>>(yl, (const uint2*)img4_p, (float*)bp_p, n);
    // x: swapped, transposed frame
    lor_kernel<true><<<nb, 256>>>(xl, (const uint2*)img4T_p, (float*)bpT_p, n);

    combine_kernel<<<NG3 / 256, 256>>>(image, eff, out);
}

// round 9
// speedup vs baseline: 1.5168x; 1.0428x over previous
#include <cuda_runtime.h>
#include <cuda_bf16.h>
#include <math.h>

// ---------------------------------------------------------------------------
// PET MLEM step. R9 = R8 (packed bf16 j-triple gather + scalar fp32 REDG
// scatter, at the LTS atomic-ALU floor) + consolidation: single prep pass,
// single uber-launch for all 3 LOR directions.
// ---------------------------------------------------------------------------

#define NG   128
#define NG3  (128 * 128 * 128)

typedef unsigned int u32;

// packed[i][j][k] = { bf16 img[i][j-1][k], bf16 img[i][j][k], bf16 img[i][j+1][k], 0 }
__device__ uint2 g_img4 [NG3];   // native orientation  (z and y directions)
__device__ uint2 g_img4T[NG3];   // transposed frame    (x direction)
__device__ float g_bp  [NG3];    // accumulator (z, y)
__device__ float g_bpT [NG3];    // transposed accumulator (x)

__constant__ float C_VOX    = 1.671875f;
__constant__ float C_XMIN   = -107.0f;
__constant__ float C_INV2S2 = 0.561975285171464f;   // pi / (2 * vox^2)

__device__ __forceinline__ u32 pack2(float a, float b) {
    __nv_bfloat162 h = __floats2bfloat162_rn(a, b);
    return *(u32*)&h;
}

// ---------------------------------------------------------------------------
// prep both packed layouts in one pass.
// Thread index order (a, c, b) with b fast:
//  - native  g_img4[a][b][c] needs image[a][b-1..b+1][c]: here we produce, for
//    fixed (a,c): entries g_img4[(a,b,c)] for all b -> reads image[a][b+o][c]
//    (stride-128 reads, 8B stores stride-128: acceptable, prep is ~1% of time)
//  - transposed g_img4T[a][b][c] = image[a][c][b-1..b+1]: contiguous reads of
//    row image[a][c][:], stores g_img4T[(a<<14)+(b<<7)+c] strided.
// ---------------------------------------------------------------------------
__global__ void prep_both_kernel(const float* __restrict__ image) {
    int tid = blockIdx.x * blockDim.x + threadIdx.x;
    if (tid >= NG3) return;
    int a = tid >> 14;
    int c = (tid >> 7) & 127;
    int b = tid & 127;

    // transposed frame: triple along original axis2 (b index), row-contiguous
    const float* row = image + (a << 14) + (c << 7);
    float tm = (b > 0)   ? row[b - 1] : 0.0f;
    float t0 =             row[b];
    float tp = (b < 127) ? row[b + 1] : 0.0f;
    uint2 wt;
    wt.x = pack2(tm, t0);
    wt.y = pack2(tp, 0.0f);
    g_img4T[(a << 14) + (b << 7) + c] = wt;

    // native frame: triple along original axis1 (c here plays j; b plays k)
    // g_img4[a][c][b] packs image[a][c-1..c+1][b]
    float nm = (c > 0)   ? image[(a << 14) + ((c - 1) << 7) + b] : 0.0f;
    float n0 =             image[(a << 14) + (c << 7) + b];
    float np = (c < 127) ? image[(a << 14) + ((c + 1) << 7) + b] : 0.0f;
    uint2 wn;
    wn.x = pack2(nm, n0);
    wn.y = pack2(np, 0.0f);
    g_img4[(a << 14) + (c << 7) + b] = wn;
}

// ---------------------------------------------------------------------------
// Uber LOR kernel: grid = 3 * nb blocks; dir = 0 (z), 1 (y), 2 (x).
// One warp per LOR; lane L owns planes {L, L+32, L+64, L+96}.
// All directions address (i, j, k) as (i<<14) + (j<<7) + k; SWAP (dirs 1, 2)
// exchanges the two transverse LOR components so j is the packed axis.
// ---------------------------------------------------------------------------
__global__ __launch_bounds__(256)
void lor_uber_kernel(const float* __restrict__ zl,
                     const float* __restrict__ yl,
                     const float* __restrict__ xl,
                     const uint2* __restrict__ img4,
                     const uint2* __restrict__ img4T,
                     float* __restrict__ bpN,
                     float* __restrict__ bpT,
                     int n, int nb) {
    const int dir = blockIdx.x / nb;
    const int bid = blockIdx.x - dir * nb;
    const int warp = bid * 8 + (threadIdx.x >> 5);
    if (warp >= n) return;
    const int lane = threadIdx.x & 31;

    const float* lors = (dir == 0) ? zl : (dir == 1) ? yl : xl;
    const uint2* img  = (dir == 2) ? img4T : img4;
    float*       bp   = (dir == 2) ? bpT : bpN;
    const bool   swap = (dir != 0);

    float p1x = lors[0 * n + warp];
    float p1y = lors[1 * n + warp];
    const float p1z = lors[2 * n + warp];
    float p2x = lors[3 * n + warp];
    float p2y = lors[4 * n + warp];
    const float p2z = lors[5 * n + warp];
    if (swap) {
        float t;
        t = p1x; p1x = p1y; p1y = t;
        t = p2x; p2x = p2y; p2y = t;
    }

    const float dx  = p2x - p1x;
    const float dy  = p2y - p1y;
    const float dzr = p2z - p1z;
    const float L   = sqrtf(dx * dx + dy * dy + dzr * dzr);
    const float dz  = (fabsf(dzr) < 1e-6f) ? 1e-6f : dzr;
    const float dl  = C_VOX * L / fabsf(dz);

    float ex[4][3];
    float ey[4][3];
    int   ib[4];
    int   jb[4];

    float acc = 0.0f;

#pragma unroll
    for (int q = 0; q < 4; q++) {
        const int   k  = lane + 32 * q;
        const float zc = C_XMIN + ((float)k + 0.5f) * C_VOX;
        const float t  = (zc - p1z) / dz;
        const bool  tok = (t >= 0.0f) && (t <= 1.0f);
        const float xs = __fadd_rn(p1x, __fmul_rn(t, dx));
        const float ys = __fadd_rn(p1y, __fmul_rn(t, dy));
        const float fi = __fadd_rn(__fdiv_rn(__fsub_rn(xs, C_XMIN), C_VOX), -0.5f);
        const float fj = __fadd_rn(__fdiv_rn(__fsub_rn(ys, C_XMIN), C_VOX), -0.5f);
        const int i0 = __float2int_rn(fi);
        const int j0 = __float2int_rn(fj);
        ib[q] = i0;
        jb[q] = j0;
        const float axc = (float)i0 - fi;
        const float ayc = (float)j0 - fj;

#pragma unroll
        for (int o = 0; o < 3; o++) {
            const float du = (axc + (float)(o - 1)) * C_VOX;
            const float eu = __expf(-du * du * C_INV2S2);
            const int   ii = i0 + o - 1;
            ex[q][o] = (tok && ii >= 0 && ii < NG) ? eu : 0.0f;

            const float dv = (ayc + (float)(o - 1)) * C_VOX;
            const float ev = __expf(-dv * dv * C_INV2S2);
            const int   jj = j0 + o - 1;
            ey[q][o] = (jj >= 0 && jj < NG) ? ev : 0.0f;
        }

        // gather: 3 packed 8B loads (j-triples), interior guaranteed when tok
        if (tok) {
            const float e0 = ey[q][0], e1 = ey[q][1], e2 = ey[q][2];
#pragma unroll
            for (int oi = 0; oi < 3; oi++) {
                const int ii = ib[q] + oi - 1;
                const uint2 w = __ldg(&img[(ii << 14) + (j0 << 7) + k]);
                const __nv_bfloat162 ab = *(const __nv_bfloat162*)&w.x;
                const __nv_bfloat162 cd = *(const __nv_bfloat162*)&w.y;
                float inner;
                inner = __fmul_rn(e0, __bfloat162float(ab.x));
                inner = fmaf(e1, __bfloat162float(ab.y), inner);
                inner = fmaf(e2, __bfloat162float(cd.x), inner);
                acc = fmaf(ex[q][oi], inner, acc);
            }
        }
    }

    // warp-reduce line integral
#pragma unroll
    for (int s = 16; s > 0; s >>= 1)
        acc += __shfl_xor_sync(0xffffffffu, acc, s);

    const float proj = acc * dl;
    const float scl  = dl / (proj + 1e-8f);

    // scatter: scalar fp32 atomics (9 per plane) — at the LTS atomic-ALU floor
#pragma unroll
    for (int q = 0; q < 4; q++) {
        const int k = lane + 32 * q;
#pragma unroll
        for (int oi = 0; oi < 3; oi++) {
            const float exi = ex[q][oi] * scl;
            const int   ii  = ib[q] + oi - 1;
#pragma unroll
            for (int oj = 0; oj < 3; oj++) {
                const float w = exi * ey[q][oj];
                if (w != 0.0f) {
                    const int jj = jb[q] + oj - 1;
                    atomicAdd(&bp[(ii << 14) + (jj << 7) + k], w);
                }
            }
        }
    }
}

// ---------------------------------------------------------------------------
// combine: out = image / (eff + 1e-8) * (bp + bpT^T)
// ---------------------------------------------------------------------------
__global__ void combine_kernel(const float* __restrict__ image,
                               const float* __restrict__ eff,
                               float* __restrict__ out) {
    int tid = blockIdx.x * blockDim.x + threadIdx.x;
    if (tid >= NG3) return;
    int a = tid >> 14;
    int b = (tid >> 7) & 127;
    int c = tid & 127;
    float bpsum = g_bp[tid] + __ldg(&g_bpT[(a << 14) + (c << 7) + b]);
    out[tid] = image[tid] / (eff[tid] + 1e-8f) * bpsum;
}

// ---------------------------------------------------------------------------
extern "C" void kernel_launch(void* const* d_in, const int* in_sizes, int n_in,
                              void* d_out, int out_size) {
    const float* image = (const float*)d_in[0];
    const float* eff   = (const float*)d_in[1];
    const float* xl    = (const float*)d_in[2];
    const float* yl    = (const float*)d_in[3];
    const float* zl    = (const float*)d_in[4];
    float*       out   = (float*)d_out;

    const int n = in_sizes[2] / 6;   // 65536

    void* img4_p  = nullptr;
    void* img4T_p = nullptr;
    void* bp_p    = nullptr;
    void* bpT_p   = nullptr;
    cudaGetSymbolAddress(&img4_p,  g_img4);
    cudaGetSymbolAddress(&img4T_p, g_img4T);
    cudaGetSymbolAddress(&bp_p,    g_bp);
    cudaGetSymbolAddress(&bpT_p,   g_bpT);

    cudaMemsetAsync(bp_p,  0, NG3 * sizeof(float));
    cudaMemsetAsync(bpT_p, 0, NG3 * sizeof(float));

    prep_both_kernel<<<NG3 / 256, 256>>>(image);

    const int nb = (n + 7) / 8;   // 8 warps (LORs) per 256-thread block

    lor_uber_kernel<<<3 * nb, 256>>>(zl, yl, xl,
                                     (const uint2*)img4_p,
                                     (const uint2*)img4T_p,
                                     (float*)bp_p, (float*)bpT_p,
                                     n, nb);

    combine_kernel<<<NG3 / 256, 256>>>(image, eff, out);
}

// round 13
// speedup vs baseline: 1.5406x; 1.0157x over previous
#include <cuda_runtime.h>
#include <math.h>

// ---------------------------------------------------------------------------
// PET MLEM step. R10: full 3x3 gather stencil packed as u8 fixed-point into
// one uint4 (LDG.128) per (lane, plane); dp4a against quantized j-weights.
// Scatter: scalar fp32 atomics (LTS floor). Single uber-launch, fused zeroing.
// ---------------------------------------------------------------------------

#define NG   128
#define NG3  (128 * 128 * 128)

typedef unsigned int  u32;
typedef unsigned char u8;

__device__ u8    g_T8[NG3];   // quantized transposed image T8[a][b][c]=q(image[a][c][b])
__device__ uint4 g_PN[NG3];   // native: PN[i][j][k] rows = image[i+oi-1][j+oj-1][k]
__device__ uint4 g_PT[NG3];   // transposed frame stencil pack (from T8)
__device__ float g_bp [NG3];  // accumulator (z, y)
__device__ float g_bpT[NG3];  // transposed accumulator (x)

__constant__ float C_VOX    = 1.671875f;
__constant__ float C_XMIN   = -107.0f;
__constant__ float C_INV2S2 = 0.561975285171464f;   // pi / (2 * vox^2)

#define QIMG    128.0f
#define DEQUANT 3.0637254902e-5f   // 1 / (128 * 255)

// ---------------------------------------------------------------------------
// K1: quantized transpose + zero both accumulators.
// ---------------------------------------------------------------------------
__global__ void prep_t8_kernel(const float* __restrict__ image) {
    int tid = blockIdx.x * blockDim.x + threadIdx.x;
    int a = tid >> 14;
    int c = (tid >> 7) & 127;
    int b = tid & 127;
    float v = image[(a << 14) + (c << 7) + b];
    g_T8[(a << 14) + (b << 7) + c] = (u8)__float2uint_rn(v * QIMG);
    g_bp[tid]  = 0.0f;
    g_bpT[tid] = 0.0f;
}

// ---------------------------------------------------------------------------
// K2: build native stencil pack PN from fp32 image (coalesced reads, k fast).
// byte layout: word x/y/z = rows oi=0/1/2; byte t of a word = oj=t (LSB first).
// ---------------------------------------------------------------------------
__global__ void prep_pn_kernel(const float* __restrict__ image) {
    int tid = blockIdx.x * blockDim.x + threadIdx.x;
    int i = tid >> 14;
    int j = (tid >> 7) & 127;
    int k = tid & 127;
    u32 w[3];
#pragma unroll
    for (int oi = 0; oi < 3; oi++) {
        int ii = min(max(i + oi - 1, 0), NG - 1);
        u32 word = 0;
#pragma unroll
        for (int oj = 0; oj < 3; oj++) {
            int jj = min(max(j + oj - 1, 0), NG - 1);
            u32 q = __float2uint_rn(image[(ii << 14) + (jj << 7) + k] * QIMG);
            word |= q << (8 * oj);
        }
        w[oi] = word;
    }
    g_PN[tid] = make_uint4(w[0], w[1], w[2], 0u);
}

// ---------------------------------------------------------------------------
// K3: build transposed-frame stencil pack PT from T8 (coalesced, K fast).
// ---------------------------------------------------------------------------
__global__ void prep_pt_kernel() {
    int tid = blockIdx.x * blockDim.x + threadIdx.x;
    int I = tid >> 14;
    int J = (tid >> 7) & 127;
    int K = tid & 127;
    u32 w[3];
#pragma unroll
    for (int oi = 0; oi < 3; oi++) {
        int ii = min(max(I + oi - 1, 0), NG - 1);
        u32 word = 0;
#pragma unroll
        for (int oj = 0; oj < 3; oj++) {
            int jj = min(max(J + oj - 1, 0), NG - 1);
            u32 q = (u32)g_T8[(ii << 14) + (jj << 7) + K];
            word |= q << (8 * oj);
        }
        w[oi] = word;
    }
    g_PT[tid] = make_uint4(w[0], w[1], w[2], 0u);
}

// ---------------------------------------------------------------------------
// Uber LOR kernel: grid = 3*nb; dir 0 = z, 1 = y, 2 = x.
// One warp per LOR; lane L owns planes {L, L+32, L+64, L+96}.
// ---------------------------------------------------------------------------
__global__ __launch_bounds__(256)
void lor_uber_kernel(const float* __restrict__ zl,
                     const float* __restrict__ yl,
                     const float* __restrict__ xl,
                     const uint4* __restrict__ pn,
                     const uint4* __restrict__ pt,
                     float* __restrict__ bpN,
                     float* __restrict__ bpT,
                     int n, int nb) {
    const int dir = blockIdx.x / nb;
    const int bid = blockIdx.x - dir * nb;
    const int warp = bid * 8 + (threadIdx.x >> 5);
    if (warp >= n) return;
    const int lane = threadIdx.x & 31;

    const float* lors = (dir == 0) ? zl : (dir == 1) ? yl : xl;
    const uint4* img  = (dir == 2) ? pt : pn;
    float*       bp   = (dir == 2) ? bpT : bpN;
    const bool   swap = (dir != 0);

    float p1x = lors[0 * n + warp];
    float p1y = lors[1 * n + warp];
    const float p1z = lors[2 * n + warp];
    float p2x = lors[3 * n + warp];
    float p2y = lors[4 * n + warp];
    const float p2z = lors[5 * n + warp];
    if (swap) {
        float t;
        t = p1x; p1x = p1y; p1y = t;
        t = p2x; p2x = p2y; p2y = t;
    }

    const float dx  = p2x - p1x;
    const float dy  = p2y - p1y;
    const float dzr = p2z - p1z;
    const float L   = sqrtf(dx * dx + dy * dy + dzr * dzr);
    const float dz  = (fabsf(dzr) < 1e-6f) ? 1e-6f : dzr;
    const float dl  = C_VOX * L / fabsf(dz);

    float ex[4][3];
    float ey[4][3];
    int   ib[4];
    int   jb[4];

    float acc = 0.0f;

#pragma unroll
    for (int q = 0; q < 4; q++) {
        const int   k  = lane + 32 * q;
        const float zc = C_XMIN + ((float)k + 0.5f) * C_VOX;
        const float t  = (zc - p1z) / dz;
        const bool  tok = (t >= 0.0f) && (t <= 1.0f);
        const float xs = __fadd_rn(p1x, __fmul_rn(t, dx));
        const float ys = __fadd_rn(p1y, __fmul_rn(t, dy));
        const float fi = __fadd_rn(__fdiv_rn(__fsub_rn(xs, C_XMIN), C_VOX), -0.5f);
        const float fj = __fadd_rn(__fdiv_rn(__fsub_rn(ys, C_XMIN), C_VOX), -0.5f);
        const int i0 = __float2int_rn(fi);
        const int j0 = __float2int_rn(fj);
        ib[q] = i0;
        jb[q] = j0;
        const float axc = (float)i0 - fi;
        const float ayc = (float)j0 - fj;

#pragma unroll
        for (int o = 0; o < 3; o++) {
            const float du = (axc + (float)(o - 1)) * C_VOX;
            const float eu = __expf(-du * du * C_INV2S2);
            const int   ii = i0 + o - 1;
            ex[q][o] = (tok && ii >= 0 && ii < NG) ? eu : 0.0f;

            const float dv = (ayc + (float)(o - 1)) * C_VOX;
            const float ev = __expf(-dv * dv * C_INV2S2);
            const int   jj = j0 + o - 1;
            ey[q][o] = (jj >= 0 && jj < NG) ? ev : 0.0f;
        }

        // gather: ONE 16B load = full 3x3 stencil; dp4a against quantized ey
        if (tok) {
            const u32 e0 = __float2uint_rn(ey[q][0] * 255.0f);
            const u32 e1 = __float2uint_rn(ey[q][1] * 255.0f);
            const u32 e2 = __float2uint_rn(ey[q][2] * 255.0f);
            const u32 eyq = e0 | (e1 << 8) | (e2 << 16);
            const uint4 w = __ldg(&img[(ib[q] << 14) + (jb[q] << 7) + k]);
            const u32 s0 = __dp4a(w.x, eyq, 0u);
            const u32 s1 = __dp4a(w.y, eyq, 0u);
            const u32 s2 = __dp4a(w.z, eyq, 0u);
            acc = fmaf(ex[q][0], (float)s0, acc);
            acc = fmaf(ex[q][1], (float)s1, acc);
            acc = fmaf(ex[q][2], (float)s2, acc);
        }
    }

    // warp-reduce line integral
#pragma unroll
    for (int s = 16; s > 0; s >>= 1)
        acc += __shfl_xor_sync(0xffffffffu, acc, s);

    const float proj = acc * dl * DEQUANT;
    const float scl  = dl / (proj + 1e-8f);

    // scatter: scalar fp32 atomics (9 per plane), full-precision weights
#pragma unroll
    for (int q = 0; q < 4; q++) {
        const int k = lane + 32 * q;
#pragma unroll
        for (int oi = 0; oi < 3; oi++) {
            const float exi = ex[q][oi] * scl;
            const int   ii  = ib[q] + oi - 1;
#pragma unroll
            for (int oj = 0; oj < 3; oj++) {
                const float w = exi * ey[q][oj];
                if (w != 0.0f) {
                    const int jj = jb[q] + oj - 1;
                    atomicAdd(&bp[(ii << 14) + (jj << 7) + k], w);
                }
            }
        }
    }
}

// ---------------------------------------------------------------------------
// combine: out = image / (eff + 1e-8) * (bp + bpT^T)
// ---------------------------------------------------------------------------
__global__ void combine_kernel(const float* __restrict__ image,
                               const float* __restrict__ eff,
                               float* __restrict__ out) {
    int tid = blockIdx.x * blockDim.x + threadIdx.x;
    int a = tid >> 14;
    int b = (tid >> 7) & 127;
    int c = tid & 127;
    float bpsum = g_bp[tid] + __ldg(&g_bpT[(a << 14) + (c << 7) + b]);
    out[tid] = image[tid] / (eff[tid] + 1e-8f) * bpsum;
}

// ---------------------------------------------------------------------------
extern "C" void kernel_launch(void* const* d_in, const int* in_sizes, int n_in,
                              void* d_out, int out_size) {
    const float* image = (const float*)d_in[0];
    const float* eff   = (const float*)d_in[1];
    const float* xl    = (const float*)d_in[2];
    const float* yl    = (const float*)d_in[3];
    const float* zl    = (const float*)d_in[4];
    float*       out   = (float*)d_out;

    const int n = in_sizes[2] / 6;   // 65536

    void* pn_p  = nullptr;
    void* pt_p  = nullptr;
    void* bp_p  = nullptr;
    void* bpT_p = nullptr;
    cudaGetSymbolAddress(&pn_p,  g_PN);
    cudaGetSymbolAddress(&pt_p,  g_PT);
    cudaGetSymbolAddress(&bp_p,  g_bp);
    cudaGetSymbolAddress(&bpT_p, g_bpT);

    prep_t8_kernel<<<NG3 / 256, 256>>>(image);   // also zeroes accumulators
    prep_pn_kernel<<<NG3 / 256, 256>>>(image);
    prep_pt_kernel<<<NG3 / 256, 256>>>();

    const int nb = (n + 7) / 8;   // 8 warps (LORs) per 256-thread block

    lor_uber_kernel<<<3 * nb, 256>>>(zl, yl, xl,
                                     (const uint4*)pn_p,
                                     (const uint4*)pt_p,
                                     (float*)bp_p, (float*)bpT_p,
                                     n, nb);

    combine_kernel<<<NG3 / 256, 256>>>(image, eff, out);
}